// round 9
// baseline (speedup 1.0000x reference)
#include <cuda_runtime.h>

#define TPB   256
#define OPT   128            // output-threads (oid) per block
#define S_OUT 256            // outputs per block (2 per oid)
#define M     11
#define T     4096
#define BB    32
#define NA    (S_OUT + 20)   // 276 amplitude window entries
#define NU    (S_OUT + 10)   // 266 sample window entries

__global__ void __launch_bounds__(TPB, 4)
gmp_kernel(const float2* __restrict__ x,
           const float*  __restrict__ W,
           float2* __restrict__ out)
{
    __shared__ float  Ak[4][NA + 2];     // amplitude powers per k
    __shared__ float2 U  [NU + 2];       // complex samples window
    __shared__ __align__(16) float wsAll[16 + 44 * 12];  // [0..10]=W0, rows of W1 padded to 12
    __shared__ float2 pc[OPT][M];        // k-partials from kh=1 half

    const int b   = blockIdx.y;
    const int t0  = blockIdx.x * S_OUT;
    const int tid = threadIdx.x;
    const int oid = tid & (OPT - 1);
    const int kh  = tid >> 7;            // 0 or 1: k-half owned
    const float2* xb = x + (size_t)b * T;

    // ---- stage amplitude powers: Ak[k][i] = |u(t0+i-20)|^(k+1), i in [0,276) ----
    for (int i = tid; i < NA; i += TPB) {
        int pos = t0 + i - 20;
        float re = 0.f, im = 0.f;
        if (pos >= 0) { float2 v = xb[pos]; re = v.x; im = v.y; }
        float a2 = re * re + im * im;
        float a  = sqrtf(a2);
        Ak[0][i] = a; Ak[1][i] = a2; Ak[2][i] = a2 * a; Ak[3][i] = a2 * a2;
    }
    // ---- stage samples: U[i] = u(t0+i-10), i in [0,266) ----
    for (int i = tid; i < NU; i += TPB) {
        int pos = t0 + i - 10;
        float re = 0.f, im = 0.f;
        if (pos >= 0) { float2 v = xb[pos]; re = v.x; im = v.y; }
        U[i] = make_float2(re, im);
    }
    // ---- stage weights: straight-line, one W1 row per thread, no div/mod loops ----
    if (tid < 16) {
        wsAll[tid] = (tid < M) ? W[tid] : 0.f;
    } else if (tid < 60) {
        int r = tid - 16;                     // row index 0..43  (r = k*11 + l)
        const float* src = W + 11 + r * 11;
        float* dst = wsAll + 16 + r * 12;
#pragma unroll
        for (int m = 0; m < M; m++) dst[m] = src[m];
        dst[11] = 0.f;                        // pad lane
    }
    __syncthreads();

    // Outputs t = t0 + 2*oid + {0,1}; this thread covers k in {2kh, 2kh+1}
    float c0[M], c1[M];
    if (kh == 0) {
#pragma unroll
        for (int m = 0; m < M; m++) { float w = wsAll[m]; c0[m] = w; c1[m] = w; }
    } else {
#pragma unroll
        for (int m = 0; m < M; m++) { c0[m] = 0.f; c1[m] = 0.f; }
    }

#pragma unroll
    for (int kk = 0; kk < 2; kk++) {
        const int k = (kh << 1) + kk;
        float win[22];                        // A_k(t0 + 2*oid - 20 + s), s=0..21
#pragma unroll
        for (int s = 0; s < 22; s += 2) {
            float2 v = *(const float2*)&Ak[k][oid * 2 + s];
            win[s] = v.x; win[s + 1] = v.y;
        }
        const float* wrow = wsAll + 16 + (k * M) * 12;
#pragma unroll
        for (int l = 0; l < M; l++) {
            float4 wa = *(const float4*)(wrow + l * 12 + 0);   // broadcast LDS.128
            float4 wb = *(const float4*)(wrow + l * 12 + 4);
            float4 wc = *(const float4*)(wrow + l * 12 + 8);
            c0[0]  = fmaf(win[l + 0],  wa.x, c0[0]);  c1[0]  = fmaf(win[l + 1],  wa.x, c1[0]);
            c0[1]  = fmaf(win[l + 1],  wa.y, c0[1]);  c1[1]  = fmaf(win[l + 2],  wa.y, c1[1]);
            c0[2]  = fmaf(win[l + 2],  wa.z, c0[2]);  c1[2]  = fmaf(win[l + 3],  wa.z, c1[2]);
            c0[3]  = fmaf(win[l + 3],  wa.w, c0[3]);  c1[3]  = fmaf(win[l + 4],  wa.w, c1[3]);
            c0[4]  = fmaf(win[l + 4],  wb.x, c0[4]);  c1[4]  = fmaf(win[l + 5],  wb.x, c1[4]);
            c0[5]  = fmaf(win[l + 5],  wb.y, c0[5]);  c1[5]  = fmaf(win[l + 6],  wb.y, c1[5]);
            c0[6]  = fmaf(win[l + 6],  wb.z, c0[6]);  c1[6]  = fmaf(win[l + 7],  wb.z, c1[6]);
            c0[7]  = fmaf(win[l + 7],  wb.w, c0[7]);  c1[7]  = fmaf(win[l + 8],  wb.w, c1[7]);
            c0[8]  = fmaf(win[l + 8],  wc.x, c0[8]);  c1[8]  = fmaf(win[l + 9],  wc.x, c1[8]);
            c0[9]  = fmaf(win[l + 9],  wc.y, c0[9]);  c1[9]  = fmaf(win[l + 10], wc.y, c1[9]);
            c0[10] = fmaf(win[l + 10], wc.z, c0[10]); c1[10] = fmaf(win[l + 11], wc.z, c1[10]);
        }
    }

    // ---- exchange k-partials ----
    if (kh == 1) {
#pragma unroll
        for (int m = 0; m < M; m++) pc[oid][m] = make_float2(c0[m], c1[m]);
    }
    __syncthreads();

    if (kh == 0) {   // combine and epilogue (one full warp-group, no divergence inside warps)
        float2 ur[12];
#pragma unroll
        for (int s = 0; s < 12; s += 2) {
            float4 v = *(const float4*)&U[oid * 2 + s];
            ur[s]     = make_float2(v.x, v.y);
            ur[s + 1] = make_float2(v.z, v.w);
        }
        float ar0 = 0.f, ai0 = 0.f, ar1 = 0.f, ai1 = 0.f;
#pragma unroll
        for (int m = 0; m < M; m++) {
            float2 p = pc[oid][m];
            float t0c = c0[m] + p.x;
            float t1c = c1[m] + p.y;
            ar0 = fmaf(ur[m].x,     t0c, ar0);  ai0 = fmaf(ur[m].y,     t0c, ai0);
            ar1 = fmaf(ur[m + 1].x, t1c, ar1);  ai1 = fmaf(ur[m + 1].y, t1c, ai1);
        }
        float4* ob = (float4*)(out + (size_t)b * T + t0) + oid;
        *ob = make_float4(ar0, ai0, ar1, ai1);
    }
}

extern "C" void kernel_launch(void* const* d_in, const int* in_sizes, int n_in,
                              void* d_out, int out_size)
{
    const float2* x = (const float2*)d_in[0];   // (32, 4096, 2) f32
    // d_in[1] = h_0 (unused by reference)
    const float*  W = (const float*)d_in[2];    // (1, 495) f32
    float2* out = (float2*)d_out;               // (32, 4096, 2) f32

    dim3 grid(T / S_OUT, BB);                   // (16, 32) = 512 blocks
    gmp_kernel<<<grid, TPB>>>(x, W, out);
}